// round 2
// baseline (speedup 1.0000x reference)
#include <cuda_runtime.h>

typedef unsigned long long ull;

#define D_MODEL 2048
#define N_STATE 256
#define RANK    64
#define LEVELS  8
#define MAX_T   16384

// ---- GEMM1: t = u @ F1   (M=T, K=2048, N=64) ----
#define TM1   128
#define KC1   32
#define NTHR1 256
#define NC1   (D_MODEL / KC1)
#define PAD1  132              // col-major u staging: [k][row], row stride 132

// ---- GEMM2: out = t @ Wcm + D*u  (M=T, K=64, N=2048) ----
#define TM2   64
#define TN2   128
#define NTHR2 256
#define PAD2  65
#define SM2_TS (TM2 * PAD2)
#define SM2_BS (RANK * TN2)
#define SM2_FLOATS (SM2_TS + SM2_BS + TN2)

// scratch (static device globals: allowed; no allocation)
__device__ float g_E[RANK * RANK];
__device__ float g_F1[D_MODEL * RANK];
__device__ float g_t[MAX_T * RANK];

// ---- packed f32x2 helpers (FFMA2 path, 2 MAC/lane/instr) ----
__device__ __forceinline__ ull pk2(float lo, float hi) {
    ull r;
    asm("mov.b64 %0, {%1, %2};" : "=l"(r) : "f"(lo), "f"(hi));
    return r;
}
__device__ __forceinline__ void fma2(ull& d, ull a, ull b) {
    asm("fma.rn.f32x2 %0, %1, %2, %0;" : "+l"(d) : "l"(a), "l"(b));
}
__device__ __forceinline__ float2 upk2(ull v) {
    float2 f;
    asm("mov.b64 {%0, %1}, %2;" : "=f"(f.x), "=f"(f.y) : "l"(v));
    return f;
}

// =====================================================================
// Kernel 0: E = Wbs @ Butterfly @ Wcr   (64x64)
// =====================================================================
__global__ void compute_E_kernel(const float* __restrict__ A_factors,
                                 const float* __restrict__ Wbs,
                                 const float* __restrict__ Wcr) {
    __shared__ float G[N_STATE * 32];   // G[n*32 + r_local]
    __shared__ float Af[LEVELS * 4];
    const int tid = threadIdx.x;
    if (tid < LEVELS * 4) Af[tid] = A_factors[tid];

    for (int half = 0; half < 2; half++) {
        __syncthreads();
        for (int i = tid; i < 32 * N_STATE; i += blockDim.x) {
            int r = i >> 8;
            int n = i & 255;
            G[n * 32 + r] = Wbs[(half * 32 + r) * N_STATE + n];
        }
        __syncthreads();
        for (int lvl = 0; lvl < LEVELS; lvl++) {
            const int stride = 128 >> lvl;
            const float a00 = Af[lvl * 4 + 0], a01 = Af[lvl * 4 + 1];
            const float a10 = Af[lvl * 4 + 2], a11 = Af[lvl * 4 + 3];
            for (int p = tid; p < 128 * 32; p += blockDim.x) {
                int r  = p & 31;
                int pi = p >> 5;
                int low = pi & (stride - 1);
                int n0  = ((pi - low) << 1) | low;
                int n1  = n0 + stride;
                float x0 = G[n0 * 32 + r];
                float x1 = G[n1 * 32 + r];
                G[n0 * 32 + r] = x0 * a00 + x1 * a10;
                G[n1 * 32 + r] = x0 * a01 + x1 * a11;
            }
            __syncthreads();
        }
        for (int o = tid; o < 32 * RANK; o += blockDim.x) {
            int rl = o >> 6;
            int j  = o & 63;
            float acc = 0.f;
            for (int n = 0; n < N_STATE; n++)
                acc += G[n * 32 + rl] * Wcr[n * RANK + j];
            g_E[(half * 32 + rl) * RANK + j] = acc;
        }
    }
}

// =====================================================================
// Kernel 1: F1 = Wbr @ E   ([2048,64] x [64,64])
// =====================================================================
__global__ void compute_F1_kernel(const float* __restrict__ Wbr) {
    __shared__ float Es[RANK * RANK];
    const int tid = threadIdx.x;
    for (int i = tid; i < RANK * RANK; i += 256) Es[i] = g_E[i];
    __syncthreads();
    const int o   = blockIdx.x * 256 + tid;
    const int row = o >> 6;
    const int j   = o & 63;
    float acc = 0.f;
#pragma unroll
    for (int k = 0; k < RANK; k++)
        acc += Wbr[row * RANK + k] * Es[k * RANK + j];
    g_F1[o] = acc;
}

// =====================================================================
// Kernel 2: t = u @ F1   (M=T, K=2048, N=64)
// 256 threads/CTA (2 warps/SMSP). u staged COLUMN-major [k][row] so the
// a-operand (two adjacent rows) loads as one LDS.64 already packed for
// fma.rn.f32x2. Per thread: 4 row-pairs x 4 cols = 16 f32x2 accumulators.
// Per k: 16 fma2 + 4 LDS.64 + 1 LDS.128 + 4 MOV -> fma-pipe bound.
// =====================================================================
__global__ __launch_bounds__(NTHR1) void gemm1_kernel(const float* __restrict__ u) {
    __shared__ float Us[KC1 * PAD1];     // [k][row]
    __shared__ float Fs[KC1 * RANK];     // [k][col]
    const int tid = threadIdx.x;
    const int tx = tid & 15;             // col group: tx*4 .. tx*4+3
    const int ty = tid >> 4;             // row group: ty*8 .. ty*8+7
    const size_t row0 = (size_t)blockIdx.x * TM1;

    ull acc[16];
#pragma unroll
    for (int i = 0; i < 16; i++) acc[i] = 0ULL;

    float4 pu[4];
    float4 pf[2];

    // prefetch chunk 0
#pragma unroll
    for (int i = 0; i < 4; i++) {
        int idx = tid + i * NTHR1;
        int r = idx >> 3, c4 = idx & 7;
        pu[i] = *(const float4*)(u + (row0 + r) * D_MODEL + c4 * 4);
    }
#pragma unroll
    for (int i = 0; i < 2; i++) {
        int idx = tid + i * NTHR1;
        int kk = idx >> 4, c4 = idx & 15;
        pf[i] = *(const float4*)(g_F1 + kk * RANK + c4 * 4);
    }

    for (int nc = 0; nc < NC1; nc++) {
        __syncthreads();
        // regs -> smem (u transposed to [k][row])
#pragma unroll
        for (int i = 0; i < 4; i++) {
            int idx = tid + i * NTHR1;
            int r = idx >> 3, c4 = idx & 7;
            Us[(c4 * 4 + 0) * PAD1 + r] = pu[i].x;
            Us[(c4 * 4 + 1) * PAD1 + r] = pu[i].y;
            Us[(c4 * 4 + 2) * PAD1 + r] = pu[i].z;
            Us[(c4 * 4 + 3) * PAD1 + r] = pu[i].w;
        }
#pragma unroll
        for (int i = 0; i < 2; i++) {
            int idx = tid + i * NTHR1;
            int kk = idx >> 4, c4 = idx & 15;
            *(float4*)&Fs[kk * RANK + c4 * 4] = pf[i];
        }
        __syncthreads();
        // prefetch next chunk
        if (nc + 1 < NC1) {
            const int k0 = (nc + 1) * KC1;
#pragma unroll
            for (int i = 0; i < 4; i++) {
                int idx = tid + i * NTHR1;
                int r = idx >> 3, c4 = idx & 7;
                pu[i] = *(const float4*)(u + (row0 + r) * D_MODEL + k0 + c4 * 4);
            }
#pragma unroll
            for (int i = 0; i < 2; i++) {
                int idx = tid + i * NTHR1;
                int kk = idx >> 4, c4 = idx & 15;
                pf[i] = *(const float4*)(g_F1 + (size_t)(k0 + kk) * RANK + c4 * 4);
            }
        }
        // compute
#pragma unroll 8
        for (int k = 0; k < KC1; k++) {
            float4 b4 = *(const float4*)&Fs[k * RANK + tx * 4];
            ull b0 = pk2(b4.x, b4.x), b1 = pk2(b4.y, b4.y);
            ull b2 = pk2(b4.z, b4.z), b3 = pk2(b4.w, b4.w);
#pragma unroll
            for (int p = 0; p < 4; p++) {
                ull a2 = *(const ull*)&Us[k * PAD1 + ty * 8 + 2 * p];  // packed rows
                fma2(acc[p * 4 + 0], a2, b0);
                fma2(acc[p * 4 + 1], a2, b1);
                fma2(acc[p * 4 + 2], a2, b2);
                fma2(acc[p * 4 + 3], a2, b3);
            }
        }
    }

    // epilogue -> g_t (row-pair accumulators: lo=even row, hi=odd row)
#pragma unroll
    for (int p = 0; p < 4; p++) {
        float2 q0 = upk2(acc[p * 4 + 0]);
        float2 q1 = upk2(acc[p * 4 + 1]);
        float2 q2 = upk2(acc[p * 4 + 2]);
        float2 q3 = upk2(acc[p * 4 + 3]);
        size_t re = row0 + ty * 8 + 2 * p;
        *(float4*)(g_t + re * RANK + tx * 4)       = make_float4(q0.x, q1.x, q2.x, q3.x);
        *(float4*)(g_t + (re + 1) * RANK + tx * 4) = make_float4(q0.y, q1.y, q2.y, q3.y);
    }
}

// =====================================================================
// Kernel 3: out = t @ Wcm + D*u   (M=T, K=64, N=2048)
// Tile 64x128, 256 threads, K=64 in one smem pass. Per thread 4 rows x
// 8 cols with column-paired f32x2 accs (b packing is free via float4).
// Smaller tile -> grid 4096, 3-4 CTAs/SM for latency hiding.
// =====================================================================
__global__ __launch_bounds__(NTHR2, 3) void gemm2_kernel(const float* __restrict__ u,
                                                         const float* __restrict__ Wcm,
                                                         const float* __restrict__ Dv,
                                                         float* __restrict__ out) {
    extern __shared__ float sm[];
    float* Ts  = sm;                  // [64][65]
    float* Bs  = sm + SM2_TS;         // [64][128]
    float* Dsh = Bs + SM2_BS;         // [128]

    const int tid = threadIdx.x;
    const int tx = tid & 15;          // cols {tx*4..+3} U {64+tx*4..+3}
    const int ty = tid >> 4;          // rows ty*4..ty*4+3
    const int ct = blockIdx.x & 15;   // 16 col tiles
    const int rt = blockIdx.x >> 4;   // 256 row tiles
    const size_t row0 = (size_t)rt * TM2;
    const int col0 = ct * TN2;

    // load t tile [64 x 64]
#pragma unroll
    for (int i = 0; i < 4; i++) {
        int idx = tid + i * NTHR2;
        int r = idx >> 4, c4 = idx & 15;
        float4 v = *(const float4*)(g_t + (row0 + r) * RANK + c4 * 4);
        float* d = &Ts[r * PAD2 + c4 * 4];
        d[0] = v.x; d[1] = v.y; d[2] = v.z; d[3] = v.w;
    }
    // load Wcm tile [64 x 128]
#pragma unroll
    for (int i = 0; i < 8; i++) {
        int idx = tid + i * NTHR2;
        int kk = idx >> 5, c4 = idx & 31;
        *(float4*)&Bs[kk * TN2 + c4 * 4] =
            *(const float4*)(Wcm + (size_t)kk * D_MODEL + col0 + c4 * 4);
    }
    if (tid < TN2 / 4) {
        *(float4*)&Dsh[tid * 4] = *(const float4*)(Dv + col0 + tid * 4);
    }
    __syncthreads();

    ull acc[16];
#pragma unroll
    for (int i = 0; i < 16; i++) acc[i] = 0ULL;

#pragma unroll 8
    for (int k = 0; k < RANK; k++) {
        float4 bA = *(const float4*)&Bs[k * TN2 + tx * 4];
        float4 bB = *(const float4*)&Bs[k * TN2 + 64 + tx * 4];
        ull b0 = pk2(bA.x, bA.y), b1 = pk2(bA.z, bA.w);
        ull b2 = pk2(bB.x, bB.y), b3 = pk2(bB.z, bB.w);
#pragma unroll
        for (int r = 0; r < 4; r++) {
            float a = Ts[(ty * 4 + r) * PAD2 + k];
            ull a2 = pk2(a, a);
            fma2(acc[r * 4 + 0], a2, b0);
            fma2(acc[r * 4 + 1], a2, b1);
            fma2(acc[r * 4 + 2], a2, b2);
            fma2(acc[r * 4 + 3], a2, b3);
        }
    }

    // epilogue: out = acc + D * u
#pragma unroll
    for (int r = 0; r < 4; r++) {
        size_t row = row0 + ty * 4 + r;
        const float* urow = u + row * D_MODEL + col0;
        float* orow = out + row * D_MODEL + col0;
        float4 u0 = *(const float4*)(urow + tx * 4);
        float4 u1 = *(const float4*)(urow + 64 + tx * 4);
        float4 d0 = *(const float4*)&Dsh[tx * 4];
        float4 d1 = *(const float4*)&Dsh[64 + tx * 4];
        float2 a0 = upk2(acc[r * 4 + 0]), a1 = upk2(acc[r * 4 + 1]);
        float2 a2 = upk2(acc[r * 4 + 2]), a3 = upk2(acc[r * 4 + 3]);
        float4 o0 = make_float4(a0.x + d0.x * u0.x, a0.y + d0.y * u0.y,
                                a1.x + d0.z * u0.z, a1.y + d0.w * u0.w);
        float4 o1 = make_float4(a2.x + d1.x * u1.x, a2.y + d1.y * u1.y,
                                a3.x + d1.z * u1.z, a3.y + d1.w * u1.w);
        *(float4*)(orow + tx * 4) = o0;
        *(float4*)(orow + 64 + tx * 4) = o1;
    }
}

extern "C" void kernel_launch(void* const* d_in, const int* in_sizes, int n_in,
                              void* d_out, int out_size) {
    const float* u   = (const float*)d_in[0];
    const float* Af  = (const float*)d_in[1];
    const float* Wbr = (const float*)d_in[2];
    const float* Wbs = (const float*)d_in[3];
    const float* Wcr = (const float*)d_in[4];
    const float* Wcm = (const float*)d_in[5];
    const float* Dv  = (const float*)d_in[6];
    float* out = (float*)d_out;

    const int T = in_sizes[0] / D_MODEL;   // 16384

    cudaFuncSetAttribute(gemm2_kernel, cudaFuncAttributeMaxDynamicSharedMemorySize,
                         SM2_FLOATS * (int)sizeof(float));

    compute_E_kernel<<<1, 256>>>(Af, Wbs, Wcr);
    compute_F1_kernel<<<(D_MODEL * RANK) / 256, 256>>>(Wbr);
    gemm1_kernel<<<T / TM1, NTHR1>>>(u);
    gemm2_kernel<<<(T / TM2) * (D_MODEL / TN2), NTHR2,
                   SM2_FLOATS * (int)sizeof(float)>>>(u, Wcm, Dv, out);
}

// round 3
// speedup vs baseline: 1.7716x; 1.7716x over previous
#include <cuda_runtime.h>

typedef unsigned long long ull;

#define D_MODEL 2048
#define N_STATE 256
#define RANK    64
#define LEVELS  8
#define MAX_T   16384

// ---- GEMM1: t = u @ F1   (M=T, K=2048, N=64), split-K ----
#define TM1    128
#define KC1    32
#define NTHR1  256
#define SPLITK 4
#define KSP    (D_MODEL / SPLITK)   // 512
#define NCSP   (KSP / KC1)          // 16
#define PAD1   132                  // col-major u staging: [k][row]

// ---- GEMM2: out = t @ Wcm + D*u  (M=T, K=64, N=2048) ----
#define TM2   128
#define TN2   128
#define NTHR2 256
#define SM2_TS (TM2 * 65)
#define SM2_BS (RANK * TN2)
#define SM2_FLOATS (SM2_TS + SM2_BS + TN2)

// ---- compute_E ----
#define E_CTAS 8
#define E_ROWS 8
#define E_SMEM ((N_STATE * RANK + E_ROWS * N_STATE) * (int)sizeof(float))

// scratch (static device globals: allowed; no allocation)
__device__ float g_E[RANK * RANK];
__device__ float g_F1[D_MODEL * RANK];
__device__ float g_t[MAX_T * RANK];
__device__ float g_tp[SPLITK][MAX_T * RANK];

// ---- packed f32x2 helpers ----
__device__ __forceinline__ ull pk2(float lo, float hi) {
    ull r;
    asm("mov.b64 %0, {%1, %2};" : "=l"(r) : "f"(lo), "f"(hi));
    return r;
}
__device__ __forceinline__ void fma2(ull& d, ull a, ull b) {
    asm("fma.rn.f32x2 %0, %1, %2, %0;" : "+l"(d) : "l"(a), "l"(b));
}
__device__ __forceinline__ float2 upk2(ull v) {
    float2 f;
    asm("mov.b64 {%0, %1}, %2;" : "=f"(f.x), "=f"(f.y) : "l"(v));
    return f;
}

// =====================================================================
// Kernel 0: E = Wbs @ Butterfly @ Wcr   (64x64)
// 8 CTAs x 256 threads; Wcr staged in smem once; butterfly on 8 rows/CTA.
// =====================================================================
__global__ __launch_bounds__(256) void compute_E_kernel(const float* __restrict__ A_factors,
                                                        const float* __restrict__ Wbs,
                                                        const float* __restrict__ Wcr) {
    extern __shared__ float esm[];
    float* Wcr_s = esm;                   // [256][64]
    float* G     = esm + N_STATE * RANK;  // [8][256]
    __shared__ float Af[LEVELS * 4];
    const int tid = threadIdx.x;
    const int r0 = blockIdx.x * E_ROWS;
    if (tid < LEVELS * 4) Af[tid] = A_factors[tid];

    // stage Wcr (coalesced float4)
#pragma unroll
    for (int i = tid; i < N_STATE * RANK / 4; i += 256)
        ((float4*)Wcr_s)[i] = ((const float4*)Wcr)[i];
    // stage 8 rows of Wbs
    for (int i = tid; i < E_ROWS * N_STATE / 4; i += 256)
        ((float4*)G)[i] = ((const float4*)(Wbs + (size_t)r0 * N_STATE))[i];
    __syncthreads();

    // butterfly: level lvl pairs indices with stride 128>>lvl
#pragma unroll
    for (int lvl = 0; lvl < LEVELS; lvl++) {
        const int stride = 128 >> lvl;
        const float a00 = Af[lvl * 4 + 0], a01 = Af[lvl * 4 + 1];
        const float a10 = Af[lvl * 4 + 2], a11 = Af[lvl * 4 + 3];
#pragma unroll
        for (int p = tid; p < E_ROWS * 128; p += 256) {
            int r  = p >> 7;
            int pi = p & 127;
            int low = pi & (stride - 1);
            int n0  = ((pi - low) << 1) | low;
            int n1  = n0 + stride;
            float x0 = G[r * N_STATE + n0];
            float x1 = G[r * N_STATE + n1];
            G[r * N_STATE + n0] = x0 * a00 + x1 * a10;
            G[r * N_STATE + n1] = x0 * a01 + x1 * a11;
        }
        __syncthreads();
    }

    // E rows [r0, r0+8) = G @ Wcr_s  (all smem-resident)
    for (int o = tid; o < E_ROWS * RANK; o += 256) {
        int r = o >> 6, j = o & 63;
        float acc = 0.f;
#pragma unroll 8
        for (int n = 0; n < N_STATE; n++)
            acc += G[r * N_STATE + n] * Wcr_s[n * RANK + j];
        g_E[(r0 + r) * RANK + j] = acc;
    }
}

// =====================================================================
// Kernel 1: F1 = Wbr @ E   ([2048,64] x [64,64])
// =====================================================================
__global__ void compute_F1_kernel(const float* __restrict__ Wbr) {
    __shared__ float Es[RANK * RANK];
    const int tid = threadIdx.x;
    for (int i = tid; i < RANK * RANK; i += 256) Es[i] = g_E[i];
    __syncthreads();
    const int o   = blockIdx.x * 256 + tid;
    const int row = o >> 6;
    const int j   = o & 63;
    float acc = 0.f;
#pragma unroll
    for (int k = 0; k < RANK; k++)
        acc += Wbr[row * RANK + k] * Es[k * RANK + j];
    g_F1[o] = acc;
}

// =====================================================================
// Kernel 2: t_partial = u @ F1 over K-slice  (split-K=4, grid 128x4)
// =====================================================================
__global__ __launch_bounds__(NTHR1) void gemm1_kernel(const float* __restrict__ u) {
    __shared__ float Us[KC1 * PAD1];     // [k][row]
    __shared__ float Fs[KC1 * RANK];     // [k][col]
    const int tid = threadIdx.x;
    const int tx = tid & 15;             // cols tx*4 .. +3
    const int ty = tid >> 4;             // rows ty*8 .. +7
    const size_t row0 = (size_t)blockIdx.x * TM1;
    const int kbase = blockIdx.y * KSP;

    ull acc[16];
#pragma unroll
    for (int i = 0; i < 16; i++) acc[i] = 0ULL;

    float4 pu[4];
    float4 pf[2];

    // prefetch chunk 0
#pragma unroll
    for (int i = 0; i < 4; i++) {
        int idx = tid + i * NTHR1;
        int r = idx >> 3, c4 = idx & 7;
        pu[i] = *(const float4*)(u + (row0 + r) * D_MODEL + kbase + c4 * 4);
    }
#pragma unroll
    for (int i = 0; i < 2; i++) {
        int idx = tid + i * NTHR1;
        int kk = idx >> 4, c4 = idx & 15;
        pf[i] = *(const float4*)(g_F1 + (size_t)(kbase + kk) * RANK + c4 * 4);
    }

    for (int nc = 0; nc < NCSP; nc++) {
        __syncthreads();
#pragma unroll
        for (int i = 0; i < 4; i++) {
            int idx = tid + i * NTHR1;
            int r = idx >> 3, c4 = idx & 7;
            Us[(c4 * 4 + 0) * PAD1 + r] = pu[i].x;
            Us[(c4 * 4 + 1) * PAD1 + r] = pu[i].y;
            Us[(c4 * 4 + 2) * PAD1 + r] = pu[i].z;
            Us[(c4 * 4 + 3) * PAD1 + r] = pu[i].w;
        }
#pragma unroll
        for (int i = 0; i < 2; i++) {
            int idx = tid + i * NTHR1;
            int kk = idx >> 4, c4 = idx & 15;
            *(float4*)&Fs[kk * RANK + c4 * 4] = pf[i];
        }
        __syncthreads();
        if (nc + 1 < NCSP) {
            const int k0 = kbase + (nc + 1) * KC1;
#pragma unroll
            for (int i = 0; i < 4; i++) {
                int idx = tid + i * NTHR1;
                int r = idx >> 3, c4 = idx & 7;
                pu[i] = *(const float4*)(u + (row0 + r) * D_MODEL + k0 + c4 * 4);
            }
#pragma unroll
            for (int i = 0; i < 2; i++) {
                int idx = tid + i * NTHR1;
                int kk = idx >> 4, c4 = idx & 15;
                pf[i] = *(const float4*)(g_F1 + (size_t)(k0 + kk) * RANK + c4 * 4);
            }
        }
#pragma unroll 8
        for (int k = 0; k < KC1; k++) {
            float4 b4 = *(const float4*)&Fs[k * RANK + tx * 4];
            ull b0 = pk2(b4.x, b4.x), b1 = pk2(b4.y, b4.y);
            ull b2 = pk2(b4.z, b4.z), b3 = pk2(b4.w, b4.w);
#pragma unroll
            for (int p = 0; p < 4; p++) {
                ull a2 = *(const ull*)&Us[k * PAD1 + ty * 8 + 2 * p];
                fma2(acc[p * 4 + 0], a2, b0);
                fma2(acc[p * 4 + 1], a2, b1);
                fma2(acc[p * 4 + 2], a2, b2);
                fma2(acc[p * 4 + 3], a2, b3);
            }
        }
    }

    float* tp = g_tp[blockIdx.y];
#pragma unroll
    for (int p = 0; p < 4; p++) {
        float2 q0 = upk2(acc[p * 4 + 0]);
        float2 q1 = upk2(acc[p * 4 + 1]);
        float2 q2 = upk2(acc[p * 4 + 2]);
        float2 q3 = upk2(acc[p * 4 + 3]);
        size_t re = row0 + ty * 8 + 2 * p;
        *(float4*)(tp + re * RANK + tx * 4)       = make_float4(q0.x, q1.x, q2.x, q3.x);
        *(float4*)(tp + (re + 1) * RANK + tx * 4) = make_float4(q0.y, q1.y, q2.y, q3.y);
    }
}

// =====================================================================
// Kernel 2b: t = sum of split-K partials
// =====================================================================
__global__ void reduce_t_kernel() {
    int i = blockIdx.x * 256 + threadIdx.x;   // float4 index
    float4 a = ((const float4*)g_tp[0])[i];
    float4 b = ((const float4*)g_tp[1])[i];
    float4 c = ((const float4*)g_tp[2])[i];
    float4 d = ((const float4*)g_tp[3])[i];
    float4 s = make_float4(a.x + b.x + c.x + d.x, a.y + b.y + c.y + d.y,
                           a.z + b.z + c.z + d.z, a.w + b.w + c.w + d.w);
    ((float4*)g_t)[i] = s;
}

// =====================================================================
// Kernel 3: out = t @ Wcm + D*u   (M=T, K=64, N=2048)  -- R1 config
// =====================================================================
__global__ __launch_bounds__(NTHR2) void gemm2_kernel(const float* __restrict__ u,
                                                      const float* __restrict__ Wcm,
                                                      const float* __restrict__ Dv,
                                                      float* __restrict__ out) {
    extern __shared__ float sm[];
    float* Ts  = sm;                  // [128][65]
    float* Bs  = sm + SM2_TS;         // [64][128]
    float* Dsh = Bs + SM2_BS;         // [128]

    const int tid = threadIdx.x;
    const int tx = tid & 15;          // cols {tx*4..+3} U {64+tx*4..+3}
    const int ty = tid >> 4;          // 8 rows each
    const int ct = blockIdx.x & 15;
    const int rt = blockIdx.x >> 4;
    const size_t row0 = (size_t)rt * TM2;
    const int col0 = ct * TN2;

#pragma unroll
    for (int i = 0; i < 8; i++) {
        int idx = tid + i * NTHR2;
        int r = idx >> 4, c4 = idx & 15;
        float4 v = *(const float4*)(g_t + (row0 + r) * RANK + c4 * 4);
        float* d = &Ts[r * 65 + c4 * 4];
        d[0] = v.x; d[1] = v.y; d[2] = v.z; d[3] = v.w;
    }
#pragma unroll
    for (int i = 0; i < 8; i++) {
        int idx = tid + i * NTHR2;
        int kk = idx >> 5, c4 = idx & 31;
        *(float4*)&Bs[kk * TN2 + c4 * 4] =
            *(const float4*)(Wcm + (size_t)kk * D_MODEL + col0 + c4 * 4);
    }
    if (tid < TN2 / 4) {
        *(float4*)&Dsh[tid * 4] = *(const float4*)(Dv + col0 + tid * 4);
    }
    __syncthreads();

    ull acc[32];
#pragma unroll
    for (int i = 0; i < 32; i++) acc[i] = 0ULL;

#pragma unroll 8
    for (int k = 0; k < RANK; k++) {
        float4 bA = *(const float4*)&Bs[k * TN2 + tx * 4];
        float4 bB = *(const float4*)&Bs[k * TN2 + 64 + tx * 4];
        ull b0 = pk2(bA.x, bA.y), b1 = pk2(bA.z, bA.w);
        ull b2 = pk2(bB.x, bB.y), b3 = pk2(bB.z, bB.w);
#pragma unroll
        for (int i = 0; i < 8; i++) {
            float a = Ts[(ty * 8 + i) * 65 + k];
            ull a2 = pk2(a, a);
            fma2(acc[i * 4 + 0], a2, b0);
            fma2(acc[i * 4 + 1], a2, b1);
            fma2(acc[i * 4 + 2], a2, b2);
            fma2(acc[i * 4 + 3], a2, b3);
        }
    }

#pragma unroll
    for (int i = 0; i < 8; i++) {
        size_t row = row0 + ty * 8 + i;
        const float* urow = u + row * D_MODEL + col0;
        float* orow = out + row * D_MODEL + col0;
        float4 u0 = *(const float4*)(urow + tx * 4);
        float4 u1 = *(const float4*)(urow + 64 + tx * 4);
        float4 d0 = *(const float4*)&Dsh[tx * 4];
        float4 d1 = *(const float4*)&Dsh[64 + tx * 4];
        float2 a0 = upk2(acc[i * 4 + 0]), a1 = upk2(acc[i * 4 + 1]);
        float2 a2 = upk2(acc[i * 4 + 2]), a3 = upk2(acc[i * 4 + 3]);
        float4 o0 = make_float4(a0.x + d0.x * u0.x, a0.y + d0.y * u0.y,
                                a1.x + d0.z * u0.z, a1.y + d0.w * u0.w);
        float4 o1 = make_float4(a2.x + d1.x * u1.x, a2.y + d1.y * u1.y,
                                a3.x + d1.z * u1.z, a3.y + d1.w * u1.w);
        *(float4*)(orow + tx * 4) = o0;
        *(float4*)(orow + 64 + tx * 4) = o1;
    }
}

extern "C" void kernel_launch(void* const* d_in, const int* in_sizes, int n_in,
                              void* d_out, int out_size) {
    const float* u   = (const float*)d_in[0];
    const float* Af  = (const float*)d_in[1];
    const float* Wbr = (const float*)d_in[2];
    const float* Wbs = (const float*)d_in[3];
    const float* Wcr = (const float*)d_in[4];
    const float* Wcm = (const float*)d_in[5];
    const float* Dv  = (const float*)d_in[6];
    float* out = (float*)d_out;

    const int T = in_sizes[0] / D_MODEL;   // 16384

    cudaFuncSetAttribute(compute_E_kernel, cudaFuncAttributeMaxDynamicSharedMemorySize, E_SMEM);
    cudaFuncSetAttribute(gemm2_kernel, cudaFuncAttributeMaxDynamicSharedMemorySize,
                         SM2_FLOATS * (int)sizeof(float));

    compute_E_kernel<<<E_CTAS, 256, E_SMEM>>>(Af, Wbs, Wcr);
    compute_F1_kernel<<<(D_MODEL * RANK) / 256, 256>>>(Wbr);
    gemm1_kernel<<<dim3(T / TM1, SPLITK), NTHR1>>>(u);
    reduce_t_kernel<<<(T * RANK / 4) / 256, 256>>>();
    gemm2_kernel<<<(T / TM2) * (D_MODEL / TN2), NTHR2,
                   SM2_FLOATS * (int)sizeof(float)>>>(u, Wcm, Dv, out);
}

// round 5
// speedup vs baseline: 1.8734x; 1.0575x over previous
#include <cuda_runtime.h>
#include <cstdint>

typedef unsigned long long ull;
typedef unsigned int uint;

#define D_MODEL 2048
#define N_STATE 256
#define RANK    64
#define LEVELS  8
#define MAX_T   16384

// ---- compute_E ----
#define E_CTAS 8
#define E_ROWS 8
#define E_SMEM ((N_STATE * RANK + E_ROWS * N_STATE) * (int)sizeof(float))

// padded row stride for fragment smem (in ull units): 32 data + 4 pad
#define RS 36

// ---- GEMM2 smem: A[128*36] + B[128*36] ull, Dsm overlays ----
#define G2_SMEM (2 * 128 * RS * (int)sizeof(ull))   // 73728

// scratch
__device__ float g_E[RANK * RANK];
__device__ ull g_F1t[RANK * (D_MODEL / 2)];     // [n][kw] (hi word | lo word<<32)
__device__ ull g_Wt[D_MODEL * (RANK / 2)];      // [n][kw], Wt[n][k]=Wcm[k][n]
__device__ ull g_t[MAX_T * (RANK / 2)];         // [row][kw] hi/lo bf16x2 pairs

// =====================================================================
// helpers
// =====================================================================
// split f32 pair (x0 -> low half) into (hi bf16x2 | lo bf16x2 << 32)
__device__ __forceinline__ ull split2(float x0, float x1) {
    uint hh;
    asm("cvt.rn.bf16x2.f32 %0, %1, %2;" : "=r"(hh) : "f"(x1), "f"(x0));
    float h0 = __uint_as_float(hh << 16);
    float h1 = __uint_as_float(hh & 0xffff0000u);
    uint ll;
    asm("cvt.rn.bf16x2.f32 %0, %1, %2;" : "=r"(ll) : "f"(x1 - h1), "f"(x0 - h0));
    return (ull)hh | ((ull)ll << 32);
}

__device__ __forceinline__ void mma16816(float* d, uint a0, uint a1, uint a2, uint a3,
                                         uint b0, uint b1) {
    asm volatile(
        "mma.sync.aligned.m16n8k16.row.col.f32.bf16.bf16.f32 "
        "{%0,%1,%2,%3}, {%4,%5,%6,%7}, {%8,%9}, {%0,%1,%2,%3};"
        : "+f"(d[0]), "+f"(d[1]), "+f"(d[2]), "+f"(d[3])
        : "r"(a0), "r"(a1), "r"(a2), "r"(a3), "r"(b0), "r"(b1));
}

// =====================================================================
// Kernel 0: E = Wbs @ Butterfly @ Wcr   (64x64)
// =====================================================================
__global__ __launch_bounds__(256) void compute_E_kernel(const float* __restrict__ A_factors,
                                                        const float* __restrict__ Wbs,
                                                        const float* __restrict__ Wcr) {
    extern __shared__ float esm[];
    float* Wcr_s = esm;
    float* G     = esm + N_STATE * RANK;
    __shared__ float Af[LEVELS * 4];
    const int tid = threadIdx.x;
    const int r0 = blockIdx.x * E_ROWS;
    if (tid < LEVELS * 4) Af[tid] = A_factors[tid];

    for (int i = tid; i < N_STATE * RANK / 4; i += 256)
        ((float4*)Wcr_s)[i] = ((const float4*)Wcr)[i];
    for (int i = tid; i < E_ROWS * N_STATE / 4; i += 256)
        ((float4*)G)[i] = ((const float4*)(Wbs + (size_t)r0 * N_STATE))[i];
    __syncthreads();

#pragma unroll
    for (int lvl = 0; lvl < LEVELS; lvl++) {
        const int stride = 128 >> lvl;
        const float a00 = Af[lvl * 4 + 0], a01 = Af[lvl * 4 + 1];
        const float a10 = Af[lvl * 4 + 2], a11 = Af[lvl * 4 + 3];
#pragma unroll
        for (int p = tid; p < E_ROWS * 128; p += 256) {
            int r  = p >> 7;
            int pi = p & 127;
            int low = pi & (stride - 1);
            int n0  = ((pi - low) << 1) | low;
            int n1  = n0 + stride;
            float x0 = G[r * N_STATE + n0];
            float x1 = G[r * N_STATE + n1];
            G[r * N_STATE + n0] = x0 * a00 + x1 * a10;
            G[r * N_STATE + n1] = x0 * a01 + x1 * a11;
        }
        __syncthreads();
    }

    for (int o = tid; o < E_ROWS * RANK; o += 256) {
        int r = o >> 6, j = o & 63;
        float acc = 0.f;
#pragma unroll 8
        for (int n = 0; n < N_STATE; n++)
            acc += G[r * N_STATE + n] * Wcr_s[n * RANK + j];
        g_E[(r0 + r) * RANK + j] = acc;
    }
}

// =====================================================================
// Kernel 1: F1t[n][kw] = hi/lo split of (Wbr @ E)^T.  32 blocks x 64 thr.
// =====================================================================
__global__ __launch_bounds__(64) void compute_F1t_kernel(const float* __restrict__ Wbr) {
    __shared__ float Ws[64 * 64];
    __shared__ float Es[64 * 64];
    __shared__ float F[64 * 64];
    const int tid = threadIdx.x;
    const int k0 = blockIdx.x * 64;
    for (int i = tid; i < 64 * 16; i += 64)
        ((float4*)Ws)[i] = ((const float4*)(Wbr + (size_t)k0 * 64))[i];
    for (int i = tid; i < 64 * 16; i += 64)
        ((float4*)Es)[i] = ((const float4*)g_E)[i];
    __syncthreads();
    // thread = local k row
#pragma unroll 4
    for (int n = 0; n < 64; n++) {
        float acc = 0.f;
#pragma unroll
        for (int r = 0; r < 64; r++)
            acc += Ws[tid * 64 + r] * Es[r * 64 + n];
        F[tid * 64 + n] = acc;
    }
    __syncthreads();
    // thread = n row; write 32 kw words
#pragma unroll 4
    for (int kw = 0; kw < 32; kw++) {
        g_F1t[tid * (D_MODEL / 2) + blockIdx.x * 32 + kw] =
            split2(F[(2 * kw) * 64 + tid], F[(2 * kw + 1) * 64 + tid]);
    }
}

// =====================================================================
// Kernel 1b: Wt[n][kw] = hi/lo split of Wcm^T. 32 blocks x 256 thr.
// =====================================================================
__global__ __launch_bounds__(256) void compute_Wcmt_kernel(const float* __restrict__ Wcm) {
    __shared__ float S[64 * 65];
    const int tid = threadIdx.x;
    const int n0 = blockIdx.x * 64;
#pragma unroll
    for (int it = 0; it < 16; it++) {
        int idx = it * 256 + tid;
        int k = idx >> 6, nn = idx & 63;
        S[nn * 65 + k] = Wcm[(size_t)k * D_MODEL + n0 + nn];
    }
    __syncthreads();
#pragma unroll
    for (int it = 0; it < 8; it++) {
        int idx = it * 256 + tid;
        int nn = idx >> 5, kw = idx & 31;
        g_Wt[(size_t)(n0 + nn) * 32 + kw] = split2(S[nn * 65 + 2 * kw], S[nn * 65 + 2 * kw + 1]);
    }
}

// =====================================================================
// Kernel 2: GEMM1 (mma.sync bf16 hi/lo): t = u @ F1
// per-CTA M=64, N=64, K=2048 (32 chunks of 64). 8 warps: warp (wm,wn):
// m-tile wm (16 rows), n-half wn (4 n8-tiles).
// =====================================================================
__global__ __launch_bounds__(256) void gemm1_mma(const float* __restrict__ u) {
    __shared__ ull Asm[64 * RS];
    __shared__ ull Bsm[64 * RS];
    const int tid = threadIdx.x;
    const int lane = tid & 31;
    const int w = tid >> 5;
    const int m0 = (w & 3) * 16;
    const int n0 = (w >> 2) * 32;
    const int g = lane >> 2;
    const int c = lane & 3;
    const size_t row0 = (size_t)blockIdx.x * 64;

    const int arow = tid >> 2;        // A staging row (0..63)
    const int akq  = tid & 3;         // quarter of row (16 floats)

    float acc[4][4];
#pragma unroll
    for (int i = 0; i < 4; i++)
#pragma unroll
        for (int j = 0; j < 4; j++) acc[i][j] = 0.f;

    float4 pu[4];
    ull pb[8];

    // prefetch chunk 0
    {
        const float* up = u + (row0 + arow) * D_MODEL + akq * 16;
#pragma unroll
        for (int j = 0; j < 4; j++) pu[j] = *(const float4*)(up + j * 4);
#pragma unroll
        for (int i = 0; i < 8; i++) {
            int idx = tid + i * 256;
            pb[i] = g_F1t[(idx >> 5) * (D_MODEL / 2) + (idx & 31)];
        }
    }

    for (int ch = 0; ch < 32; ch++) {
        if (ch > 0) __syncthreads();
        // store staged chunk (convert u to hi/lo bf16 word pairs)
        {
            const int kwb = akq * 8;
#pragma unroll
            for (int j = 0; j < 4; j++) {
                Asm[arow * RS + kwb + 2 * j]     = split2(pu[j].x, pu[j].y);
                Asm[arow * RS + kwb + 2 * j + 1] = split2(pu[j].z, pu[j].w);
            }
#pragma unroll
            for (int i = 0; i < 8; i++) {
                int idx = tid + i * 256;
                Bsm[(idx >> 5) * RS + (idx & 31)] = pb[i];
            }
        }
        __syncthreads();
        // prefetch next
        if (ch + 1 < 32) {
            const float* up = u + (row0 + arow) * D_MODEL + (ch + 1) * 64 + akq * 16;
#pragma unroll
            for (int j = 0; j < 4; j++) pu[j] = *(const float4*)(up + j * 4);
#pragma unroll
            for (int i = 0; i < 8; i++) {
                int idx = tid + i * 256;
                pb[i] = g_F1t[(idx >> 5) * (D_MODEL / 2) + (ch + 1) * 32 + (idx & 31)];
            }
        }
        // compute 4 k-steps of 16
#pragma unroll
        for (int ks = 0; ks < 4; ks++) {
            const int kwb = ks * 8;
            ull a0 = Asm[(m0 + g) * RS + kwb + c];
            ull a1 = Asm[(m0 + g + 8) * RS + kwb + c];
            ull a2 = Asm[(m0 + g) * RS + kwb + 4 + c];
            ull a3 = Asm[(m0 + g + 8) * RS + kwb + 4 + c];
            uint ah0 = (uint)a0, al0 = (uint)(a0 >> 32);
            uint ah1 = (uint)a1, al1 = (uint)(a1 >> 32);
            uint ah2 = (uint)a2, al2 = (uint)(a2 >> 32);
            uint ah3 = (uint)a3, al3 = (uint)(a3 >> 32);
#pragma unroll
            for (int nt = 0; nt < 4; nt++) {
                ull b0 = Bsm[(n0 + nt * 8 + g) * RS + kwb + c];
                ull b1 = Bsm[(n0 + nt * 8 + g) * RS + kwb + 4 + c];
                uint bh0 = (uint)b0, bl0 = (uint)(b0 >> 32);
                uint bh1 = (uint)b1, bl1 = (uint)(b1 >> 32);
                mma16816(acc[nt], ah0, ah1, ah2, ah3, bh0, bh1);
                mma16816(acc[nt], ah0, ah1, ah2, ah3, bl0, bl1);
                mma16816(acc[nt], al0, al1, al2, al3, bh0, bh1);
            }
        }
    }

    // epilogue: split accumulators to hi/lo bf16 pairs, store t
#pragma unroll
    for (int nt = 0; nt < 4; nt++) {
        int kw = (n0 >> 1) + nt * 4 + c;
        size_t r = row0 + m0 + g;
        g_t[r * 32 + kw]       = split2(acc[nt][0], acc[nt][1]);
        g_t[(r + 8) * 32 + kw] = split2(acc[nt][2], acc[nt][3]);
    }
}

// =====================================================================
// Kernel 3: GEMM2 (mma.sync bf16 hi/lo): out = t @ Wcm + D*u
// per-CTA tile 128x128, K=64 one pass. 8 warps: warp (wm,wn):
// 2 m16-tiles x 8 n8-tiles each.
// =====================================================================
__global__ __launch_bounds__(256) void gemm2_mma(const float* __restrict__ u,
                                                 const float* __restrict__ Dv,
                                                 float* __restrict__ out) {
    extern __shared__ ull dsm[];
    ull* Asm = dsm;                 // [128*RS]
    ull* Bsm = dsm + 128 * RS;
    float* Dsm = (float*)dsm;       // [128][132] overlay after compute

    const int tid = threadIdx.x;
    const int ct = blockIdx.x & 15;
    const int rt = blockIdx.x >> 4;
    const size_t row0 = (size_t)rt * 128;
    const int col0 = ct * 128;

#pragma unroll
    for (int i = 0; i < 16; i++) {
        int idx = tid + i * 256;
        int r = idx >> 5, kw = idx & 31;
        Asm[r * RS + kw] = g_t[(row0 + r) * 32 + kw];
        Bsm[r * RS + kw] = g_Wt[(size_t)(col0 + r) * 32 + kw];
    }
    __syncthreads();

    const int lane = tid & 31;
    const int w = tid >> 5;
    const int g = lane >> 2;
    const int c = lane & 3;
    const int m0 = (w & 3) * 32;
    const int n0 = (w >> 2) * 64;

    float acc[2][8][4];
#pragma unroll
    for (int a = 0; a < 2; a++)
#pragma unroll
        for (int b = 0; b < 8; b++)
#pragma unroll
            for (int d = 0; d < 4; d++) acc[a][b][d] = 0.f;

#pragma unroll
    for (int ks = 0; ks < 4; ks++) {
        const int kwb = ks * 8;
        uint ah[2][4], al[2][4];
#pragma unroll
        for (int mt = 0; mt < 2; mt++) {
            int mr = m0 + mt * 16 + g;
            ull a0 = Asm[mr * RS + kwb + c];
            ull a1 = Asm[(mr + 8) * RS + kwb + c];
            ull a2 = Asm[mr * RS + kwb + 4 + c];
            ull a3 = Asm[(mr + 8) * RS + kwb + 4 + c];
            ah[mt][0] = (uint)a0; al[mt][0] = (uint)(a0 >> 32);
            ah[mt][1] = (uint)a1; al[mt][1] = (uint)(a1 >> 32);
            ah[mt][2] = (uint)a2; al[mt][2] = (uint)(a2 >> 32);
            ah[mt][3] = (uint)a3; al[mt][3] = (uint)(a3 >> 32);
        }
#pragma unroll
        for (int nt = 0; nt < 8; nt++) {
            ull b0 = Bsm[(n0 + nt * 8 + g) * RS + kwb + c];
            ull b1 = Bsm[(n0 + nt * 8 + g) * RS + kwb + 4 + c];
            uint bh0 = (uint)b0, bl0 = (uint)(b0 >> 32);
            uint bh1 = (uint)b1, bl1 = (uint)(b1 >> 32);
#pragma unroll
            for (int mt = 0; mt < 2; mt++) {
                mma16816(acc[mt][nt], ah[mt][0], ah[mt][1], ah[mt][2], ah[mt][3], bh0, bh1);
                mma16816(acc[mt][nt], ah[mt][0], ah[mt][1], ah[mt][2], ah[mt][3], bl0, bl1);
                mma16816(acc[mt][nt], al[mt][0], al[mt][1], al[mt][2], al[mt][3], bh0, bh1);
            }
        }
    }
    __syncthreads();   // all warps done reading tiles

    // stage accumulators into Dsm for coalesced epilogue
#pragma unroll
    for (int mt = 0; mt < 2; mt++) {
#pragma unroll
        for (int nt = 0; nt < 8; nt++) {
            int r = m0 + mt * 16 + g;
            int cc = n0 + nt * 8 + c * 2;
            *(float2*)&Dsm[r * 132 + cc]       = make_float2(acc[mt][nt][0], acc[mt][nt][1]);
            *(float2*)&Dsm[(r + 8) * 132 + cc] = make_float2(acc[mt][nt][2], acc[mt][nt][3]);
        }
    }
    __syncthreads();

#pragma unroll
    for (int it = 0; it < 16; it++) {
        int idx = it * 256 + tid;
        int r = idx >> 5, c4 = idx & 31;
        size_t grow = row0 + r;
        int gcol = col0 + c4 * 4;
        float4 dv = *(const float4*)(Dv + gcol);
        float4 uv = *(const float4*)(u + grow * D_MODEL + gcol);
        float4 o;
        o.x = Dsm[r * 132 + c4 * 4 + 0] + dv.x * uv.x;
        o.y = Dsm[r * 132 + c4 * 4 + 1] + dv.y * uv.y;
        o.z = Dsm[r * 132 + c4 * 4 + 2] + dv.z * uv.z;
        o.w = Dsm[r * 132 + c4 * 4 + 3] + dv.w * uv.w;
        *(float4*)(out + grow * D_MODEL + gcol) = o;
    }
}

extern "C" void kernel_launch(void* const* d_in, const int* in_sizes, int n_in,
                              void* d_out, int out_size) {
    const float* u   = (const float*)d_in[0];
    const float* Af  = (const float*)d_in[1];
    const float* Wbr = (const float*)d_in[2];
    const float* Wbs = (const float*)d_in[3];
    const float* Wcr = (const float*)d_in[4];
    const float* Wcm = (const float*)d_in[5];
    const float* Dv  = (const float*)d_in[6];
    float* out = (float*)d_out;

    const int T = in_sizes[0] / D_MODEL;   // 16384

    cudaFuncSetAttribute(compute_E_kernel, cudaFuncAttributeMaxDynamicSharedMemorySize, E_SMEM);
    cudaFuncSetAttribute(gemm2_mma, cudaFuncAttributeMaxDynamicSharedMemorySize, G2_SMEM);

    compute_E_kernel<<<E_CTAS, 256, E_SMEM>>>(Af, Wbs, Wcr);
    compute_F1t_kernel<<<32, 64>>>(Wbr);
    compute_Wcmt_kernel<<<32, 256>>>(Wcm);
    gemm1_mma<<<T / 64, 256>>>(u);
    gemm2_mma<<<(T / 128) * (D_MODEL / 128), 256, G2_SMEM>>>(u, Dv, out);
}